// round 17
// baseline (speedup 1.0000x reference)
#include <cuda_runtime.h>
#include <cuda.h>
#include <cstdint>
#include <cstddef>

// 1x1 conv as GEMM on HMMA (mma.sync tf32), sm_103 target.
// out[b,o,p] = sum_i W[i,o] * x[b,i,p];  B=32, CIN=COUT=128, HW=16384.
// R17: DECOUPLED pipeline - no __syncthreads in the main loop. 3 B buffers,
// each with a full mbarrier (TMA expect_tx) and an empty mbarrier (count 8,
// per-warp arrive). Warps run independently; fast warps lead slow warps by
// up to ~3 chunks, so per-warp stalls stop summing across the CTA.
// B staged via TMA (cp.async.bulk.tensor.2d, SW128). A = W^T 64KB
// XOR-swizzled. Tile M=128 x N=128 x K=128; 8 warps 2(M)x4(N), warp m64n32.
// SMEM ~112KB -> 2 CTAs/SM.

#define HW      16384
#define NCH     128
#define TILE_N  128
#define NTILES  4096
#define GRID    304
#define NTHREADS 256

#define A_OFF     0                   // 16384 words
#define B_OFF     16384               // 3 buffers x 4096 words (32r x 128px)
#define MBAR_WOFF 28672               // full[3] then empty[3], 8B each
#define SMEM_WORDS (28672 + 16)
#define SMEM_BYTES (SMEM_WORDS * 4)   // 114752 B -> 2 CTAs/SM

__device__ __forceinline__ uint32_t smem_u32(const void* p) {
    uint32_t a;
    asm("{ .reg .u64 t; cvta.to.shared.u64 t, %1; cvt.u32.u64 %0, t; }" : "=r"(a) : "l"(p));
    return a;
}

#define MBARRIER_INIT(addr, cnt) \
    asm volatile("mbarrier.init.shared.b64 [%0], %1;" :: "r"(addr), "r"(cnt) : "memory")
#define MBARRIER_EXPECT_TX(addr, bytes) \
    asm volatile("mbarrier.arrive.expect_tx.shared.b64 _, [%0], %1;" \
        :: "r"(addr), "r"(bytes) : "memory")
#define MBARRIER_ARRIVE(addr) \
    asm volatile("mbarrier.arrive.shared.b64 _, [%0];" :: "r"(addr) : "memory")
#define MBAR_WAIT(addr, par) do {                                              \
    uint32_t _m = (addr); uint32_t _p = (par);                                 \
    asm volatile("{\n\t.reg .pred P1;\n\t"                                     \
        "W_%=: mbarrier.try_wait.parity.shared.b64 P1, [%0], %1;\n\t"          \
        "@P1 bra.uni D_%=;\n\t bra.uni W_%=;\n\tD_%=:\n\t}"                    \
        :: "r"(_m), "r"(_p) : "memory");                                       \
} while (0)

#define TMA_LOAD_2D(dst, tmap, cx, cy, mbar) \
    asm volatile("cp.async.bulk.tensor.2d.shared::cta.global.tile.mbarrier::complete_tx::bytes " \
        "[%0], [%1, {%2, %3}], [%4];" \
        :: "r"(dst), "l"(tmap), "r"(cx), "r"(cy), "r"(mbar) : "memory")

__device__ __forceinline__ void mma_tf32(float c[4], uint32_t a0, uint32_t a1,
                                         uint32_t a2, uint32_t a3,
                                         uint32_t b0, uint32_t b1) {
    asm volatile(
        "mma.sync.aligned.m16n8k8.row.col.f32.tf32.tf32.f32 "
        "{%0,%1,%2,%3},{%4,%5,%6,%7},{%8,%9},{%0,%1,%2,%3};"
        : "+f"(c[0]), "+f"(c[1]), "+f"(c[2]), "+f"(c[3])
        : "r"(a0), "r"(a1), "r"(a2), "r"(a3), "r"(b0), "r"(b1));
}

__global__ __launch_bounds__(NTHREADS, 2)
void conv1x1_tma_kernel(const float* __restrict__ w,
                        float* __restrict__ out,
                        const __grid_constant__ CUtensorMap tmap)
{
    extern __shared__ __align__(128) float smem[];
    const uint32_t sb = smem_u32(smem);
    const int tid = threadIdx.x;
    const int lid = tid & 31;
    const int wid = tid >> 5;
    const int mw  = wid & 1;          // M half
    const int nw  = wid >> 1;         // N quarter
    const int bid = blockIdx.x;
    const int lr  = lid >> 2;         // 0..7
    const int lc  = lid & 3;          // 0..3

    // ---- W^T -> A smem once, RN-rounded tf32, XOR-swizzled:
    // word(o,k) = o*128 + ((k>>3)*8 ^ ((o&3)<<3)) + (k&3)*2 + ((k>>2)&1)
    for (int i = tid; i < NCH * NCH; i += NTHREADS) {
        int k = i >> 7, o = i & 127;
        float v = __ldg(&w[k * NCH + o]);
        uint32_t t;
        asm("cvt.rna.tf32.f32 %0, %1;" : "=r"(t) : "f"(v));
        int wd = o * 128 + (((k >> 3) * 8) ^ ((o & 3) << 3)) + (k & 3) * 2 + ((k >> 2) & 1);
        smem[A_OFF + wd] = __uint_as_float(t);
    }
    const uint32_t mbF = sb + MBAR_WOFF * 4u;        // full[3]
    const uint32_t mbE = mbF + 24;                   // empty[3]
    if (tid == 0) {
        #pragma unroll
        for (int b = 0; b < 3; b++) {
            MBARRIER_INIT(mbF + b * 8, 1);
            MBARRIER_INIT(mbE + b * 8, 8);
        }
    }
    __syncthreads();                                 // only barrier in the kernel

    const int n     = (NTILES - bid + GRID - 1) / GRID;
    const int total = 4 * n;                         // 32-row chunks

    // ---- TMA chunk issue (thread 0): 4 boxes of 32px x 32 k-rows into buf
    auto issue_chunk = [&](int g, int buf) {
        int t  = bid + (g >> 2) * GRID;
        int b  = t >> 7;
        int p0 = (t & 127) * TILE_N;
        int cy = b * NCH + (g & 3) * 32;
        MBARRIER_EXPECT_TX(mbF + buf * 8, 16384u);
        uint32_t dst = sb + (uint32_t)(B_OFF + buf * 4096) * 4u;
        #pragma unroll
        for (int r = 0; r < 4; r++)
            TMA_LOAD_2D(dst + r * 4096u, &tmap, p0 + r * 32, cy, mbF + buf * 8);
    };

    if (tid == 0) {
        issue_chunk(0, 0);
        if (total > 1) issue_chunk(1, 1);
    }

    const int kxor = (lr & 3) << 3;
    const float* Asm = smem + A_OFF + (mw * 64 + lr) * 128 + lc * 2;
    float acc[4][4][4];

    // incremental mod-3 / round counters
    int cbuf = 0, crnd = 0;          // consumer: chunk g
    int pbuf = 2, prnd = 0;          // producer: chunk g+2

    #pragma unroll 1
    for (int g = 0; g < total; g++) {
        // producer: refill pbuf with chunk g+2 (needs empty round prnd-1 done)
        if (tid == 0 && g + 2 < total) {
            if (prnd > 0) MBAR_WAIT(mbE + pbuf * 8, (prnd - 1) & 1);
            issue_chunk(g + 2, pbuf);
        }

        MBAR_WAIT(mbF + cbuf * 8, crnd & 1);         // chunk g resident

        if ((g & 3) == 0) {
            #pragma unroll
            for (int mt = 0; mt < 4; mt++)
                #pragma unroll
                for (int nt = 0; nt < 4; nt++)
                    #pragma unroll
                    for (int q = 0; q < 4; q++) acc[mt][nt][q] = 0.f;
        }

        // B region: 32px column-group nw, TMA SW128 layout:
        // word(row, c) = row*32 + (c ^ ((row&7)<<2)),  c = lr + nt*8
        const float* Bs = smem + B_OFF + cbuf * 4096 + nw * 1024;
        const int kk0 = (g & 3) * 4;

        #pragma unroll
        for (int kl = 0; kl < 4; kl++) {
            const int kk = kk0 + kl;
            uint32_t af[4][4];
            #pragma unroll
            for (int mt = 0; mt < 4; mt++) {
                const float* pa = Asm + mt * 16 * 128 + ((kk * 8) ^ kxor);
                asm volatile("ld.shared.v2.b32 {%0,%1}, [%2];"
                    : "=r"(af[mt][0]), "=r"(af[mt][2]) : "r"(smem_u32(pa)));
                asm volatile("ld.shared.v2.b32 {%0,%1}, [%2];"
                    : "=r"(af[mt][1]), "=r"(af[mt][3]) : "r"(smem_u32(pa + 8 * 128)));
            }
            uint32_t bf[4][2];
            const int r0 = kl * 8 + lc;
            #pragma unroll
            for (int nt = 0; nt < 4; nt++) {
                int c = lr + nt * 8;
                bf[nt][0] = __float_as_uint(Bs[r0 * 32 + (c ^ (lc << 2))]);
                bf[nt][1] = __float_as_uint(Bs[(r0 + 4) * 32 + (c ^ (lc << 2) ^ 16)]);
            }
            #pragma unroll
            for (int mt = 0; mt < 4; mt++)
                #pragma unroll
                for (int nt = 0; nt < 4; nt++)
                    mma_tf32(acc[mt][nt], af[mt][0], af[mt][1], af[mt][2], af[mt][3],
                             bf[nt][0], bf[nt][1]);
        }

        // warp done with buffer: per-warp arrive (after MMAs -> LDS data landed)
        if (lid == 0) MBARRIER_ARRIVE(mbE + cbuf * 8);

        if ((g & 3) == 3) {                          // tile finished -> epilogue
            int t  = bid + (g >> 2) * GRID;
            int b  = t >> 7;
            int p0 = (t & 127) * TILE_N;
            float* ob = out + (size_t)b * NCH * HW + p0 + nw * 32 + lc * 2;
            #pragma unroll
            for (int mt = 0; mt < 4; mt++) {
                float* orow = ob + (size_t)(mw * 64 + mt * 16 + lr) * HW;
                #pragma unroll
                for (int nt = 0; nt < 4; nt++) {
                    *(float2*)(orow + nt * 8)          = make_float2(acc[mt][nt][0], acc[mt][nt][1]);
                    *(float2*)(orow + 8 * HW + nt * 8) = make_float2(acc[mt][nt][2], acc[mt][nt][3]);
                }
            }
        }

        // advance counters
        if (++cbuf == 3) { cbuf = 0; crnd++; }
        if (++pbuf == 3) { pbuf = 0; prnd++; }
    }
}

typedef CUresult (*PFN_tmapEncode)(
    CUtensorMap*, CUtensorMapDataType, cuuint32_t, void*,
    const cuuint64_t*, const cuuint64_t*, const cuuint32_t*, const cuuint32_t*,
    CUtensorMapInterleave, CUtensorMapSwizzle, CUtensorMapL2promotion,
    CUtensorMapFloatOOBfill);

extern "C" void kernel_launch(void* const* d_in, const int* in_sizes, int n_in,
                              void* d_out, int out_size)
{
    const float* x = (const float*)d_in[0];   // (32,128,128,128) fp32
    const float* w = (const float*)d_in[1];   // (128,128) fp32
    float* out = (float*)d_out;

    PFN_tmapEncode encode = nullptr;
    cudaDriverEntryPointQueryResult qr;
    cudaGetDriverEntryPoint("cuTensorMapEncodeTiled", (void**)&encode,
                            cudaEnableDefault, &qr);
    CUtensorMap tmap;
    cuuint64_t gdim[2]    = { (cuuint64_t)HW, (cuuint64_t)(NCH * 32) };
    cuuint64_t gstride[1] = { (cuuint64_t)HW * 4 };
    cuuint32_t box[2]     = { 32, 32 };
    cuuint32_t estride[2] = { 1, 1 };
    encode(&tmap, CU_TENSOR_MAP_DATA_TYPE_FLOAT32, 2, (void*)x,
           gdim, gstride, box, estride,
           CU_TENSOR_MAP_INTERLEAVE_NONE, CU_TENSOR_MAP_SWIZZLE_128B,
           CU_TENSOR_MAP_L2_PROMOTION_L2_128B, CU_TENSOR_MAP_FLOAT_OOB_FILL_NONE);

    cudaFuncSetAttribute(conv1x1_tma_kernel,
                         cudaFuncAttributeMaxDynamicSharedMemorySize, SMEM_BYTES);
    conv1x1_tma_kernel<<<GRID, NTHREADS, SMEM_BYTES>>>(w, out, tmap);
}